// round 6
// baseline (speedup 1.0000x reference)
#include <cuda_runtime.h>

// LIF SNN scan: T=1024 timesteps, B*N = 65536 independent columns.
// out layout: [ spikes (T*BN) | v_final (BN) | i_final (BN) ]
// R5: PF 32 -> 64 (self-throttles at ~55 outstanding LDG/warp ~= 97 KB/SM in
// flight) + block 128 -> 64 (grid 1024: 7-vs-6 CTA/SM skew instead of 4-vs-3).

#define T_STEPS 1024
#define BN      65536
#define PF      64

__global__ __launch_bounds__(64, 4)
void snn_lif_kernel(const float* __restrict__ x, float* __restrict__ out) {
    const int idx = blockIdx.x * blockDim.x + threadIdx.x;  // column id
    const float* xp = x + idx;
    float*       zp = out + idx;

    float v   = 0.0f;   // membrane potential
    float cur = 0.0f;   // synaptic current

    // prologue: fill the prefetch ring
    float xbuf[PF];
    #pragma unroll
    for (int j = 0; j < PF; ++j)
        xbuf[j] = __ldg(xp + (long)j * BN);

    // dt*tau_mem_inv = 0.1, (1 - dt*tau_syn_inv) = 0.8, v_th = 1, v_reset = 0
    for (int t0 = 0; t0 < T_STEPS - PF; t0 += PF) {
        #pragma unroll
        for (int j = 0; j < PF; ++j) {
            const float xt = xbuf[j];
            // immediately re-issue this slot for t0+PF+j (keeps the ring full)
            xbuf[j] = __ldg(xp + (long)(t0 + PF + j) * BN);

            const float v_dec = fmaf(0.1f, cur - v, v);
            const bool  fired = (v_dec > 1.0f);
            const float z     = fired ? 1.0f : 0.0f;
            v   = fired ? 0.0f : v_dec;
            cur = fmaf(cur, 0.8f, xt);

            zp[(long)(t0 + j) * BN] = z;
        }
    }

    // epilogue: last PF steps, no prefetch
    #pragma unroll
    for (int j = 0; j < PF; ++j) {
        const float xt = xbuf[j];

        const float v_dec = fmaf(0.1f, cur - v, v);
        const bool  fired = (v_dec > 1.0f);
        const float z     = fired ? 1.0f : 0.0f;
        v   = fired ? 0.0f : v_dec;
        cur = fmaf(cur, 0.8f, xt);

        zp[(long)(T_STEPS - PF + j) * BN] = z;
    }

    // final state after the full scan
    out[(long)T_STEPS * BN + idx]      = v;
    out[(long)T_STEPS * BN + BN + idx] = cur;
}

extern "C" void kernel_launch(void* const* d_in, const int* in_sizes, int n_in,
                              void* d_out, int out_size) {
    const float* x   = (const float*)d_in[0];
    float*       out = (float*)d_out;
    (void)in_sizes; (void)n_in; (void)out_size;

    snn_lif_kernel<<<BN / 64, 64>>>(x, out);
}

// round 7
// speedup vs baseline: 1.1198x; 1.1198x over previous
#include <cuda_runtime.h>

// LIF SNN scan: T=1024 timesteps, B*N = 65536 independent columns.
// out layout: [ spikes (T*BN) | v_final (BN) | i_final (BN) ]
// R6: exact R4 body (PF=32: under the ~55/warp LSU cap, regs=80) with
// block 128 -> 64 only: grid=1024 -> 7-vs-6 CTA/SM skew (14%) vs 4-vs-3 (33%).

#define T_STEPS 1024
#define BN      65536
#define PF      32

__global__ __launch_bounds__(64, 8)
void snn_lif_kernel(const float* __restrict__ x, float* __restrict__ out) {
    const int idx = blockIdx.x * blockDim.x + threadIdx.x;  // column id
    const float* xp = x + idx;
    float*       zp = out + idx;

    float v   = 0.0f;   // membrane potential
    float cur = 0.0f;   // synaptic current

    // prologue: fill the prefetch ring (32 independent LDGs in flight)
    float xbuf[PF];
    #pragma unroll
    for (int j = 0; j < PF; ++j)
        xbuf[j] = __ldg(xp + (long)j * BN);

    // dt*tau_mem_inv = 0.1, (1 - dt*tau_syn_inv) = 0.8, v_th = 1, v_reset = 0
    for (int t0 = 0; t0 < T_STEPS - PF; t0 += PF) {
        #pragma unroll
        for (int j = 0; j < PF; ++j) {
            const float xt = xbuf[j];
            // immediately re-issue this slot for t0+PF+j (keeps the ring full)
            xbuf[j] = __ldg(xp + (long)(t0 + PF + j) * BN);

            const float v_dec = fmaf(0.1f, cur - v, v);
            const bool  fired = (v_dec > 1.0f);
            const float z     = fired ? 1.0f : 0.0f;
            v   = fired ? 0.0f : v_dec;
            cur = fmaf(cur, 0.8f, xt);

            zp[(long)(t0 + j) * BN] = z;
        }
    }

    // epilogue: last PF steps, no prefetch
    #pragma unroll
    for (int j = 0; j < PF; ++j) {
        const float xt = xbuf[j];

        const float v_dec = fmaf(0.1f, cur - v, v);
        const bool  fired = (v_dec > 1.0f);
        const float z     = fired ? 1.0f : 0.0f;
        v   = fired ? 0.0f : v_dec;
        cur = fmaf(cur, 0.8f, xt);

        zp[(long)(T_STEPS - PF + j) * BN] = z;
    }

    // final state after the full scan
    out[(long)T_STEPS * BN + idx]      = v;
    out[(long)T_STEPS * BN + BN + idx] = cur;
}

extern "C" void kernel_launch(void* const* d_in, const int* in_sizes, int n_in,
                              void* d_out, int out_size) {
    const float* x   = (const float*)d_in[0];
    float*       out = (float*)d_out;
    (void)in_sizes; (void)n_in; (void)out_size;

    snn_lif_kernel<<<BN / 64, 64>>>(x, out);
}